// round 13
// baseline (speedup 1.0000x reference)
#include <cuda_runtime.h>
#include <cuda_bf16.h>
#include <cstdint>

#define N_NODES 50000
#define N_EDGES 500000
#define D 128
#define EPS 1e-5f

// ---------------- device scratch (no allocations allowed) ----------------
__device__ __align__(16) __nv_bfloat16 g_xn[N_NODES * D];        // 12.8 MB
__device__ __align__(16) __nv_bfloat16 g_Pb[N_NODES * 512];      // 51.2 MB  [Ps_d|Ps_g|Pd_d|Pd_g] bf16
__device__ __align__(16) __nv_bfloat16 g_BnT[512 * D];           // node weights, [out_col][k]
__device__ __align__(16) __nv_bfloat16 g_WeT[256 * D];           // edge weights, [out_col][k]

// ---------------- weight prep: transpose + bf16 convert ----------------
__global__ void prep_kernel(const float* __restrict__ W) {
    int i = blockIdx.x * blockDim.x + threadIdx.x;   // 65536 threads
    if (i < 512 * D) {
        int j = i >> 7, k = i & 127;
        float w = (j < 256) ? W[k * 256 + j] : W[(128 + k) * 256 + (j - 256)];
        g_BnT[i] = __float2bfloat16_rn(w);
    }
    if (i < 256 * D) {
        int n = i >> 7, k = i & 127;
        g_WeT[i] = __float2bfloat16_rn(W[(256 + k) * 256 + n]);
    }
}

// ---------------- per-node LayerNorm -> bf16 ----------------
__global__ void node_ln_kernel(const float* __restrict__ x,
                               const float* __restrict__ gamma,
                               const float* __restrict__ beta) {
    int lane = threadIdx.x & 31;
    int row = blockIdx.x * (blockDim.x >> 5) + (threadIdx.x >> 5);
    if (row >= N_NODES) return;
    float4 v = ((const float4*)(x + (size_t)row * D))[lane];
    float s = v.x + v.y + v.z + v.w;
    float q = v.x * v.x + v.y * v.y + v.z * v.z + v.w * v.w;
    #pragma unroll
    for (int o = 16; o; o >>= 1) {
        s += __shfl_xor_sync(0xffffffffu, s, o);
        q += __shfl_xor_sync(0xffffffffu, q, o);
    }
    float mu = s * (1.0f / 128.0f);
    float var = q * (1.0f / 128.0f) - mu * mu;
    float sc = rsqrtf(var + EPS);
    float4 g4 = ((const float4*)gamma)[lane];
    float4 b4 = ((const float4*)beta)[lane];
    float y0 = (v.x - mu) * sc * g4.x + b4.x;
    float y1 = (v.y - mu) * sc * g4.y + b4.y;
    float y2 = (v.z - mu) * sc * g4.z + b4.z;
    float y3 = (v.w - mu) * sc * g4.w + b4.w;
    __nv_bfloat162 t0 = __floats2bfloat162_rn(y0, y1);
    __nv_bfloat162 t1 = __floats2bfloat162_rn(y2, y3);
    uint2 pk = make_uint2(*(uint32_t*)&t0, *(uint32_t*)&t1);
    ((uint2*)(g_xn + (size_t)row * D))[lane] = pk;
}

// ---------------- PTX helpers ----------------
__device__ __forceinline__ void mma16816(float* c, const uint32_t* a, uint32_t b0, uint32_t b1) {
    asm volatile(
        "mma.sync.aligned.m16n8k16.row.col.f32.bf16.bf16.f32 "
        "{%0,%1,%2,%3},{%4,%5,%6,%7},{%8,%9},{%0,%1,%2,%3};"
        : "+f"(c[0]), "+f"(c[1]), "+f"(c[2]), "+f"(c[3])
        : "r"(a[0]), "r"(a[1]), "r"(a[2]), "r"(a[3]), "r"(b0), "r"(b1));
}
__device__ __forceinline__ void ldm_x4(uint32_t& r0, uint32_t& r1, uint32_t& r2, uint32_t& r3,
                                       uint32_t addr) {
    asm volatile("ldmatrix.sync.aligned.m8n8.x4.shared.b16 {%0,%1,%2,%3}, [%4];"
                 : "=r"(r0), "=r"(r1), "=r"(r2), "=r"(r3) : "r"(addr));
}
__device__ __forceinline__ uint32_t smem_u32(const void* p) {
    return (uint32_t)__cvta_generic_to_shared(p);
}
__device__ __forceinline__ void cp_async16(uint32_t dst, const void* src) {
    asm volatile("cp.async.cg.shared.global [%0], [%1], 16;" :: "r"(dst), "l"(src));
}
__device__ __forceinline__ void cp_async_wait_all() {
    asm volatile("cp.async.commit_group;\n\tcp.async.wait_group 0;" ::: "memory");
}
// sigmoid(x) via ex2.approx + rcp.approx (2 MUFU + 2 ALU, vs ~18-instr IEEE div path)
__device__ __forceinline__ float fast_sig(float x) {
    float e, r;
    asm("ex2.approx.f32 %0, %1;" : "=f"(e) : "f"(-1.4426950408889634f * x));
    asm("rcp.approx.f32 %0, %1;" : "=f"(r) : "f"(1.0f + e));
    return r;
}

// smem strides: A/B rows are 136 bf16 = 272 bytes (16B-aligned, rows 4 banks apart)
#define ASTRIDE_B 272
#define SA_BYTES  (64 * 272)    // 17408
#define SB_BYTES  (256 * 272)   // 69632
#define SMEM_MMA  (SA_BYTES + SB_BYTES)   // 87040  -> 2 CTAs/SM

// MMA core: CTA tile M=64,N=256,K=128; 16 warps 4(M)x4(N); warp tile 16x64.
__device__ __forceinline__ void mma_core(uint32_t sAu, uint32_t sBu, int wm, int wn,
                                         int lane, float acc[8][4]) {
    uint32_t aAddr = sAu + (wm * 16 + (lane & 15)) * ASTRIDE_B + ((lane >> 4) << 4);
    uint32_t bAddr = sBu + (wn * 64 + ((lane >> 4) << 3) + (lane & 7)) * ASTRIDE_B
                         + (((lane >> 3) & 1) << 4);
    #pragma unroll
    for (int k0 = 0; k0 < 128; k0 += 16) {
        uint32_t a[4];
        ldm_x4(a[0], a[1], a[2], a[3], aAddr + k0 * 2);
        #pragma unroll
        for (int jp = 0; jp < 4; jp++) {
            uint32_t b0, b1, b2, b3;
            ldm_x4(b0, b1, b2, b3, bAddr + jp * 16 * ASTRIDE_B + k0 * 2);
            mma16816(acc[jp * 2],     a, b0, b1);
            mma16816(acc[jp * 2 + 1], a, b2, b3);
        }
    }
}

// ---------------- node GEMM: P = xn @ [W0|W1]  (+bias on src half), bf16 out ----------------
__global__ __launch_bounds__(512, 2) void node_gemm_kernel(const float* __restrict__ b) {
    extern __shared__ char smem[];
    char* sA = smem;
    char* sB = smem + SA_BYTES;
    uint32_t sAu = smem_u32(sA), sBu = smem_u32(sB);
    int tid = threadIdx.x, lane = tid & 31, wid = tid >> 5;
    int g = lane >> 2, tig = lane & 3;
    int wm = wid & 3, wn = wid >> 2;
    int n0 = blockIdx.x * 64;
    int bn = blockIdx.y;   // 0: Ps (+bias), 1: Pd

    const uint4* Bg = (const uint4*)(g_BnT + bn * 256 * D);
    #pragma unroll
    for (int it = 0; it < 8; it++) {
        int v = tid + it * 512;
        int row = v >> 4, c = v & 15;
        cp_async16(sBu + row * ASTRIDE_B + c * 16, Bg + v);
    }
    #pragma unroll
    for (int it = 0; it < 2; it++) {
        int v = tid + it * 512;
        int row = v >> 4, c = v & 15;
        int rr = min(n0 + row, N_NODES - 1);
        cp_async16(sAu + row * ASTRIDE_B + c * 16, ((const uint4*)g_xn) + rr * 16 + c);
    }
    cp_async_wait_all();
    __syncthreads();

    float acc[8][4];
    #pragma unroll
    for (int j = 0; j < 8; j++)
        #pragma unroll
        for (int q = 0; q < 4; q++) acc[j][q] = 0.0f;

    mma_core(sAu, sBu, wm, wn, lane, acc);

    #pragma unroll
    for (int j = 0; j < 8; j++) {
        int colw = wn * 64 + j * 8 + tig * 2;
        float b0v = 0.0f, b1v = 0.0f;
        if (bn == 0) { float2 bb = ((const float2*)b)[colw >> 1]; b0v = bb.x; b1v = bb.y; }
        int col = bn * 256 + colw;
        int row = n0 + wm * 16 + g;
        if (row < N_NODES) {
            __nv_bfloat162 h = __floats2bfloat162_rn(acc[j][0] + b0v, acc[j][1] + b1v);
            *(uint32_t*)(g_Pb + (size_t)row * 512 + col) = *(uint32_t*)&h;
        }
        if (row + 8 < N_NODES) {
            __nv_bfloat162 h = __floats2bfloat162_rn(acc[j][2] + b0v, acc[j][3] + b1v);
            *(uint32_t*)(g_Pb + (size_t)(row + 8) * 512 + col) = *(uint32_t*)&h;
        }
    }
}

// ---------------- fused edge kernel (512 threads, 16 warps, 2 CTAs/SM) ----------------
#define RSTRIDE 260
__global__ __launch_bounds__(512, 2) void edge_kernel(
    const int* __restrict__ ei, const float* __restrict__ ea,
    const float* __restrict__ gamma, const float* __restrict__ beta,
    float* __restrict__ out)
{
    extern __shared__ char smem[];
    char* sA = smem;
    char* sB = smem + SA_BYTES;
    float* sRaw = (float*)smem;                 // reused after MMA
    uint32_t sAu = smem_u32(sA), sBu = smem_u32(sB);
    int tid = threadIdx.x, lane = tid & 31, wid = tid >> 5;
    int g = lane >> 2, tig = lane & 3;
    int wm = wid & 3, wn = wid >> 2;
    int e0 = blockIdx.x * 64;

    #pragma unroll
    for (int it = 0; it < 8; it++) {                   // B: WeT via cp.async (overlaps A convert)
        int v = tid + it * 512;
        int row = v >> 4, c = v & 15;
        cp_async16(sBu + row * ASTRIDE_B + c * 16, ((const uint4*)g_WeT) + v);
    }
    #pragma unroll
    for (int it = 0; it < 4; it++) {                   // A: edge_attr fp32 -> bf16
        int v = tid + it * 512;                        // 0..2047, 32 float4 per row
        int row = v >> 5, c4 = (v & 31) * 4;
        int e = min(e0 + row, N_EDGES - 1);
        float4 f = *(const float4*)(ea + (size_t)e * D + c4);
        __nv_bfloat162 t0 = __floats2bfloat162_rn(f.x, f.y);
        __nv_bfloat162 t1 = __floats2bfloat162_rn(f.z, f.w);
        char* p = sA + row * ASTRIDE_B + c4 * 2;
        *(uint32_t*)p = *(uint32_t*)&t0;
        *(uint32_t*)(p + 4) = *(uint32_t*)&t1;
    }
    cp_async_wait_all();
    __syncthreads();

    float acc[8][4];
    #pragma unroll
    for (int j = 0; j < 8; j++)
        #pragma unroll
        for (int q = 0; q < 4; q++) acc[j][q] = 0.0f;

    mma_core(sAu, sBu, wm, wn, lane, acc);

    __syncthreads();                                   // done reading sA/sB
    #pragma unroll
    for (int j = 0; j < 8; j++) {
        int col = wn * 64 + j * 8 + tig * 2;
        int row = wm * 16 + g;
        *(float2*)(sRaw + row * RSTRIDE + col) = make_float2(acc[j][0], acc[j][1]);
        *(float2*)(sRaw + (row + 8) * RSTRIDE + col) = make_float2(acc[j][2], acc[j][3]);
    }
    __syncthreads();

    // phase 2: each warp owns 4 rows, processed as 2 batches of 2 (reg pressure)
    float4 gm = ((const float4*)gamma)[lane];
    float4 bt = ((const float4*)beta)[lane];
    #pragma unroll
    for (int rb = 0; rb < 2; rb++) {
        int sn[2], dn[2];
        #pragma unroll
        for (int r = 0; r < 2; r++) {
            int e = min(e0 + wid * 4 + rb * 2 + r, N_EDGES - 1);
            sn[r] = ei[e];
            dn[r] = ei[N_EDGES + e];
        }
        uint2 psd[2], psg[2], pdd[2], pdg[2];
        float4 a4[2];
        #pragma unroll
        for (int r = 0; r < 2; r++) {
            const __nv_bfloat16* Ps = g_Pb + (size_t)sn[r] * 512;
            const __nv_bfloat16* Pd = g_Pb + (size_t)dn[r] * 512 + 256;
            psd[r] = *(const uint2*)(Ps + lane * 4);
            psg[r] = *(const uint2*)(Ps + 128 + lane * 4);
            pdd[r] = *(const uint2*)(Pd + lane * 4);
            pdg[r] = *(const uint2*)(Pd + 128 + lane * 4);
            int e = min(e0 + wid * 4 + rb * 2 + r, N_EDGES - 1);
            a4[r] = *(const float4*)(ea + (size_t)e * D + lane * 4);
        }
        #pragma unroll
        for (int r = 0; r < 2; r++) {
            int row = wid * 4 + rb * 2 + r;
            int e = e0 + row;
            if (e >= N_EDGES) break;
            const float* pr = sRaw + row * RSTRIDE;
            float4 rd = *(const float4*)(pr + lane * 4);          // delta part of ea@W2
            float4 rg = *(const float4*)(pr + 128 + lane * 4);    // gate part
            float2 s0 = __bfloat1622float2(*(__nv_bfloat162*)&psd[r].x);
            float2 s1 = __bfloat1622float2(*(__nv_bfloat162*)&psd[r].y);
            float2 s2 = __bfloat1622float2(*(__nv_bfloat162*)&psg[r].x);
            float2 s3 = __bfloat1622float2(*(__nv_bfloat162*)&psg[r].y);
            float2 d0 = __bfloat1622float2(*(__nv_bfloat162*)&pdd[r].x);
            float2 d1 = __bfloat1622float2(*(__nv_bfloat162*)&pdd[r].y);
            float2 d2 = __bfloat1622float2(*(__nv_bfloat162*)&pdg[r].x);
            float2 d3 = __bfloat1622float2(*(__nv_bfloat162*)&pdg[r].y);
            float dl[4], gt[4];
            dl[0] = fmaxf(rd.x + s0.x + d0.x, 0.0f);
            dl[1] = fmaxf(rd.y + s0.y + d0.y, 0.0f);
            dl[2] = fmaxf(rd.z + s1.x + d1.x, 0.0f);
            dl[3] = fmaxf(rd.w + s1.y + d1.y, 0.0f);
            gt[0] = fmaxf(rg.x + s2.x + d2.x, 0.0f);
            gt[1] = fmaxf(rg.y + s2.y + d2.y, 0.0f);
            gt[2] = fmaxf(rg.z + s3.x + d3.x, 0.0f);
            gt[3] = fmaxf(rg.w + s3.y + d3.y, 0.0f);
            float o[4];
            o[0] = fmaf(dl[0], fast_sig(gt[0]), a4[r].x);
            o[1] = fmaf(dl[1], fast_sig(gt[1]), a4[r].y);
            o[2] = fmaf(dl[2], fast_sig(gt[2]), a4[r].z);
            o[3] = fmaf(dl[3], fast_sig(gt[3]), a4[r].w);
            float s1r = o[0] + o[1] + o[2] + o[3];
            float s2r = o[0] * o[0] + o[1] * o[1] + o[2] * o[2] + o[3] * o[3];
            #pragma unroll
            for (int off = 16; off; off >>= 1) {
                s1r += __shfl_xor_sync(0xffffffffu, s1r, off);
                s2r += __shfl_xor_sync(0xffffffffu, s2r, off);
            }
            float mu = s1r * (1.0f / 128.0f);
            float var = s2r * (1.0f / 128.0f) - mu * mu;
            float sc = rsqrtf(var + EPS);
            float4 w4;
            w4.x = (o[0] - mu) * sc * gm.x + bt.x;
            w4.y = (o[1] - mu) * sc * gm.y + bt.y;
            w4.z = (o[2] - mu) * sc * gm.z + bt.z;
            w4.w = (o[3] - mu) * sc * gm.w + bt.w;
            *(float4*)(out + (size_t)e * D + lane * 4) = w4;
        }
    }
}

// ---------------- launch ----------------
extern "C" void kernel_launch(void* const* d_in, const int* in_sizes, int n_in,
                              void* d_out, int out_size) {
    const float* x  = (const float*)d_in[0];
    const int*   ei = (const int*)d_in[1];
    const float* ea = (const float*)d_in[2];
    const float* W  = (const float*)d_in[3];
    const float* b  = (const float*)d_in[4];
    const float* ng = (const float*)d_in[5];
    const float* nb = (const float*)d_in[6];
    const float* eg = (const float*)d_in[7];
    const float* eb = (const float*)d_in[8];
    float* out = (float*)d_out;

    cudaFuncSetAttribute(node_gemm_kernel, cudaFuncAttributeMaxDynamicSharedMemorySize,
                         SMEM_MMA);
    cudaFuncSetAttribute(edge_kernel, cudaFuncAttributeMaxDynamicSharedMemorySize,
                         SMEM_MMA);

    prep_kernel<<<256, 256>>>(W);
    node_ln_kernel<<<(N_NODES + 7) / 8, 256>>>(x, ng, nb);
    node_gemm_kernel<<<dim3((N_NODES + 63) / 64, 2), 512, SMEM_MMA>>>(b);
    edge_kernel<<<(N_EDGES + 63) / 64, 512, SMEM_MMA>>>(ei, ea, eg, eb, out);
}

// round 14
// speedup vs baseline: 1.0087x; 1.0087x over previous
#include <cuda_runtime.h>
#include <cuda_bf16.h>
#include <cstdint>

#define N_NODES 50000
#define N_EDGES 500000
#define D 128
#define EPS 1e-5f

// ---------------- device scratch (no allocations allowed) ----------------
__device__ __align__(16) __nv_bfloat16 g_xn[N_NODES * D];        // 12.8 MB
__device__ __align__(16) __nv_bfloat16 g_Pb[N_NODES * 512];      // 51.2 MB  [Ps_d|Ps_g|Pd_d|Pd_g] bf16
__device__ __align__(16) __nv_bfloat16 g_BnT[512 * D];           // node weights, [out_col][k]
__device__ __align__(16) __nv_bfloat16 g_WeT[256 * D];           // edge weights, [out_col][k]

// ---------------- weight prep: transpose + bf16 convert ----------------
__global__ void prep_kernel(const float* __restrict__ W) {
    int i = blockIdx.x * blockDim.x + threadIdx.x;   // 65536 threads
    if (i < 512 * D) {
        int j = i >> 7, k = i & 127;
        float w = (j < 256) ? W[k * 256 + j] : W[(128 + k) * 256 + (j - 256)];
        g_BnT[i] = __float2bfloat16_rn(w);
    }
    if (i < 256 * D) {
        int n = i >> 7, k = i & 127;
        g_WeT[i] = __float2bfloat16_rn(W[(256 + k) * 256 + n]);
    }
}

// ---------------- per-node LayerNorm -> bf16 ----------------
__global__ void node_ln_kernel(const float* __restrict__ x,
                               const float* __restrict__ gamma,
                               const float* __restrict__ beta) {
    int lane = threadIdx.x & 31;
    int row = blockIdx.x * (blockDim.x >> 5) + (threadIdx.x >> 5);
    if (row >= N_NODES) return;
    float4 v = ((const float4*)(x + (size_t)row * D))[lane];
    float s = v.x + v.y + v.z + v.w;
    float q = v.x * v.x + v.y * v.y + v.z * v.z + v.w * v.w;
    #pragma unroll
    for (int o = 16; o; o >>= 1) {
        s += __shfl_xor_sync(0xffffffffu, s, o);
        q += __shfl_xor_sync(0xffffffffu, q, o);
    }
    float mu = s * (1.0f / 128.0f);
    float var = q * (1.0f / 128.0f) - mu * mu;
    float sc = rsqrtf(var + EPS);
    float4 g4 = ((const float4*)gamma)[lane];
    float4 b4 = ((const float4*)beta)[lane];
    float y0 = (v.x - mu) * sc * g4.x + b4.x;
    float y1 = (v.y - mu) * sc * g4.y + b4.y;
    float y2 = (v.z - mu) * sc * g4.z + b4.z;
    float y3 = (v.w - mu) * sc * g4.w + b4.w;
    __nv_bfloat162 t0 = __floats2bfloat162_rn(y0, y1);
    __nv_bfloat162 t1 = __floats2bfloat162_rn(y2, y3);
    uint2 pk = make_uint2(*(uint32_t*)&t0, *(uint32_t*)&t1);
    ((uint2*)(g_xn + (size_t)row * D))[lane] = pk;
}

// ---------------- PTX helpers ----------------
__device__ __forceinline__ void mma16816(float* c, const uint32_t* a, uint32_t b0, uint32_t b1) {
    asm volatile(
        "mma.sync.aligned.m16n8k16.row.col.f32.bf16.bf16.f32 "
        "{%0,%1,%2,%3},{%4,%5,%6,%7},{%8,%9},{%0,%1,%2,%3};"
        : "+f"(c[0]), "+f"(c[1]), "+f"(c[2]), "+f"(c[3])
        : "r"(a[0]), "r"(a[1]), "r"(a[2]), "r"(a[3]), "r"(b0), "r"(b1));
}
__device__ __forceinline__ void ldm_x4(uint32_t& r0, uint32_t& r1, uint32_t& r2, uint32_t& r3,
                                       uint32_t addr) {
    asm volatile("ldmatrix.sync.aligned.m8n8.x4.shared.b16 {%0,%1,%2,%3}, [%4];"
                 : "=r"(r0), "=r"(r1), "=r"(r2), "=r"(r3) : "r"(addr));
}
__device__ __forceinline__ uint32_t smem_u32(const void* p) {
    return (uint32_t)__cvta_generic_to_shared(p);
}
__device__ __forceinline__ void cp_async16(uint32_t dst, const void* src) {
    asm volatile("cp.async.cg.shared.global [%0], [%1], 16;" :: "r"(dst), "l"(src));
}
__device__ __forceinline__ void cp_async_wait_all() {
    asm volatile("cp.async.commit_group;\n\tcp.async.wait_group 0;" ::: "memory");
}
// sigmoid(x) via ex2.approx + rcp.approx (2 MUFU + 2 ALU, vs ~18-instr IEEE div path)
__device__ __forceinline__ float fast_sig(float x) {
    float e, r;
    asm("ex2.approx.f32 %0, %1;" : "=f"(e) : "f"(-1.4426950408889634f * x));
    asm("rcp.approx.f32 %0, %1;" : "=f"(r) : "f"(1.0f + e));
    return r;
}

// smem strides: A/B rows are 136 bf16 = 272 bytes (16B-aligned, rows 4 banks apart)
#define ASTRIDE_B 272
#define SA_BYTES  (64 * 272)    // 17408
#define SB_BYTES  (256 * 272)   // 69632
#define SMEM_MMA  (SA_BYTES + SB_BYTES)   // 87040  -> 2 CTAs/SM

// MMA core: CTA tile M=64,N=256,K=128; 16 warps 4(M)x4(N); warp tile 16x64.
__device__ __forceinline__ void mma_core(uint32_t sAu, uint32_t sBu, int wm, int wn,
                                         int lane, float acc[8][4]) {
    uint32_t aAddr = sAu + (wm * 16 + (lane & 15)) * ASTRIDE_B + ((lane >> 4) << 4);
    uint32_t bAddr = sBu + (wn * 64 + ((lane >> 4) << 3) + (lane & 7)) * ASTRIDE_B
                         + (((lane >> 3) & 1) << 4);
    #pragma unroll
    for (int k0 = 0; k0 < 128; k0 += 16) {
        uint32_t a[4];
        ldm_x4(a[0], a[1], a[2], a[3], aAddr + k0 * 2);
        #pragma unroll
        for (int jp = 0; jp < 4; jp++) {
            uint32_t b0, b1, b2, b3;
            ldm_x4(b0, b1, b2, b3, bAddr + jp * 16 * ASTRIDE_B + k0 * 2);
            mma16816(acc[jp * 2],     a, b0, b1);
            mma16816(acc[jp * 2 + 1], a, b2, b3);
        }
    }
}

// ---------------- node GEMM: P = xn @ [W0|W1]  (+bias on src half), bf16 out ----------------
__global__ __launch_bounds__(512, 2) void node_gemm_kernel(const float* __restrict__ b) {
    extern __shared__ char smem[];
    char* sA = smem;
    char* sB = smem + SA_BYTES;
    uint32_t sAu = smem_u32(sA), sBu = smem_u32(sB);
    int tid = threadIdx.x, lane = tid & 31, wid = tid >> 5;
    int g = lane >> 2, tig = lane & 3;
    int wm = wid & 3, wn = wid >> 2;
    int n0 = blockIdx.x * 64;
    int bn = blockIdx.y;   // 0: Ps (+bias), 1: Pd

    const uint4* Bg = (const uint4*)(g_BnT + bn * 256 * D);
    #pragma unroll
    for (int it = 0; it < 8; it++) {
        int v = tid + it * 512;
        int row = v >> 4, c = v & 15;
        cp_async16(sBu + row * ASTRIDE_B + c * 16, Bg + v);
    }
    #pragma unroll
    for (int it = 0; it < 2; it++) {
        int v = tid + it * 512;
        int row = v >> 4, c = v & 15;
        int rr = min(n0 + row, N_NODES - 1);
        cp_async16(sAu + row * ASTRIDE_B + c * 16, ((const uint4*)g_xn) + rr * 16 + c);
    }
    cp_async_wait_all();
    __syncthreads();

    float acc[8][4];
    #pragma unroll
    for (int j = 0; j < 8; j++)
        #pragma unroll
        for (int q = 0; q < 4; q++) acc[j][q] = 0.0f;

    mma_core(sAu, sBu, wm, wn, lane, acc);

    #pragma unroll
    for (int j = 0; j < 8; j++) {
        int colw = wn * 64 + j * 8 + tig * 2;
        float b0v = 0.0f, b1v = 0.0f;
        if (bn == 0) { float2 bb = ((const float2*)b)[colw >> 1]; b0v = bb.x; b1v = bb.y; }
        int col = bn * 256 + colw;
        int row = n0 + wm * 16 + g;
        if (row < N_NODES) {
            __nv_bfloat162 h = __floats2bfloat162_rn(acc[j][0] + b0v, acc[j][1] + b1v);
            *(uint32_t*)(g_Pb + (size_t)row * 512 + col) = *(uint32_t*)&h;
        }
        if (row + 8 < N_NODES) {
            __nv_bfloat162 h = __floats2bfloat162_rn(acc[j][2] + b0v, acc[j][3] + b1v);
            *(uint32_t*)(g_Pb + (size_t)(row + 8) * 512 + col) = *(uint32_t*)&h;
        }
    }
}

// ---------------- fused edge kernel (512 threads, 16 warps, 2 CTAs/SM) ----------------
#define RSTRIDE 260
__global__ __launch_bounds__(512, 2) void edge_kernel(
    const int* __restrict__ ei, const float* __restrict__ ea,
    const float* __restrict__ gamma, const float* __restrict__ beta,
    float* __restrict__ out)
{
    extern __shared__ char smem[];
    char* sA = smem;
    char* sB = smem + SA_BYTES;
    float* sRaw = (float*)smem;                 // reused after MMA
    uint32_t sAu = smem_u32(sA), sBu = smem_u32(sB);
    int tid = threadIdx.x, lane = tid & 31, wid = tid >> 5;
    int g = lane >> 2, tig = lane & 3;
    int wm = wid & 3, wn = wid >> 2;
    int e0 = blockIdx.x * 64;

    #pragma unroll
    for (int it = 0; it < 8; it++) {                   // B: WeT via cp.async (overlaps A convert)
        int v = tid + it * 512;
        int row = v >> 4, c = v & 15;
        cp_async16(sBu + row * ASTRIDE_B + c * 16, ((const uint4*)g_WeT) + v);
    }
    #pragma unroll
    for (int it = 0; it < 4; it++) {                   // A: edge_attr fp32 -> bf16
        int v = tid + it * 512;                        // 0..2047, 32 float4 per row
        int row = v >> 5, c4 = (v & 31) * 4;
        int e = min(e0 + row, N_EDGES - 1);
        float4 f = *(const float4*)(ea + (size_t)e * D + c4);
        __nv_bfloat162 t0 = __floats2bfloat162_rn(f.x, f.y);
        __nv_bfloat162 t1 = __floats2bfloat162_rn(f.z, f.w);
        char* p = sA + row * ASTRIDE_B + c4 * 2;
        *(uint32_t*)p = *(uint32_t*)&t0;
        *(uint32_t*)(p + 4) = *(uint32_t*)&t1;
    }
    cp_async_wait_all();
    __syncthreads();

    float acc[8][4];
    #pragma unroll
    for (int j = 0; j < 8; j++)
        #pragma unroll
        for (int q = 0; q < 4; q++) acc[j][q] = 0.0f;

    mma_core(sAu, sBu, wm, wn, lane, acc);

    __syncthreads();                                   // done reading sA/sB
    #pragma unroll
    for (int j = 0; j < 8; j++) {
        int col = wn * 64 + j * 8 + tig * 2;
        int row = wm * 16 + g;
        *(float2*)(sRaw + row * RSTRIDE + col) = make_float2(acc[j][0], acc[j][1]);
        *(float2*)(sRaw + (row + 8) * RSTRIDE + col) = make_float2(acc[j][2], acc[j][3]);
    }
    __syncthreads();

    // phase 2: each warp owns 4 rows, processed as 2 batches of 2 (reg pressure)
    float4 gm = ((const float4*)gamma)[lane];
    float4 bt = ((const float4*)beta)[lane];
    #pragma unroll
    for (int rb = 0; rb < 2; rb++) {
        int sn[2], dn[2];
        #pragma unroll
        for (int r = 0; r < 2; r++) {
            int e = min(e0 + wid * 4 + rb * 2 + r, N_EDGES - 1);
            sn[r] = ei[e];
            dn[r] = ei[N_EDGES + e];
        }
        uint2 psd[2], psg[2], pdd[2], pdg[2];
        float4 a4[2];
        #pragma unroll
        for (int r = 0; r < 2; r++) {
            const __nv_bfloat16* Ps = g_Pb + (size_t)sn[r] * 512;
            const __nv_bfloat16* Pd = g_Pb + (size_t)dn[r] * 512 + 256;
            psd[r] = *(const uint2*)(Ps + lane * 4);
            psg[r] = *(const uint2*)(Ps + 128 + lane * 4);
            pdd[r] = *(const uint2*)(Pd + lane * 4);
            pdg[r] = *(const uint2*)(Pd + 128 + lane * 4);
            int e = min(e0 + wid * 4 + rb * 2 + r, N_EDGES - 1);
            a4[r] = *(const float4*)(ea + (size_t)e * D + lane * 4);
        }
        #pragma unroll
        for (int r = 0; r < 2; r++) {
            int row = wid * 4 + rb * 2 + r;
            int e = e0 + row;
            if (e >= N_EDGES) break;
            const float* pr = sRaw + row * RSTRIDE;
            float4 rd = *(const float4*)(pr + lane * 4);          // delta part of ea@W2
            float4 rg = *(const float4*)(pr + 128 + lane * 4);    // gate part
            float2 s0 = __bfloat1622float2(*(__nv_bfloat162*)&psd[r].x);
            float2 s1 = __bfloat1622float2(*(__nv_bfloat162*)&psd[r].y);
            float2 s2 = __bfloat1622float2(*(__nv_bfloat162*)&psg[r].x);
            float2 s3 = __bfloat1622float2(*(__nv_bfloat162*)&psg[r].y);
            float2 d0 = __bfloat1622float2(*(__nv_bfloat162*)&pdd[r].x);
            float2 d1 = __bfloat1622float2(*(__nv_bfloat162*)&pdd[r].y);
            float2 d2 = __bfloat1622float2(*(__nv_bfloat162*)&pdg[r].x);
            float2 d3 = __bfloat1622float2(*(__nv_bfloat162*)&pdg[r].y);
            float dl[4], gt[4];
            dl[0] = fmaxf(rd.x + s0.x + d0.x, 0.0f);
            dl[1] = fmaxf(rd.y + s0.y + d0.y, 0.0f);
            dl[2] = fmaxf(rd.z + s1.x + d1.x, 0.0f);
            dl[3] = fmaxf(rd.w + s1.y + d1.y, 0.0f);
            gt[0] = fmaxf(rg.x + s2.x + d2.x, 0.0f);
            gt[1] = fmaxf(rg.y + s2.y + d2.y, 0.0f);
            gt[2] = fmaxf(rg.z + s3.x + d3.x, 0.0f);
            gt[3] = fmaxf(rg.w + s3.y + d3.y, 0.0f);
            float o[4];
            o[0] = fmaf(dl[0], fast_sig(gt[0]), a4[r].x);
            o[1] = fmaf(dl[1], fast_sig(gt[1]), a4[r].y);
            o[2] = fmaf(dl[2], fast_sig(gt[2]), a4[r].z);
            o[3] = fmaf(dl[3], fast_sig(gt[3]), a4[r].w);
            float s1r = o[0] + o[1] + o[2] + o[3];
            float s2r = o[0] * o[0] + o[1] * o[1] + o[2] * o[2] + o[3] * o[3];
            #pragma unroll
            for (int off = 16; off; off >>= 1) {
                s1r += __shfl_xor_sync(0xffffffffu, s1r, off);
                s2r += __shfl_xor_sync(0xffffffffu, s2r, off);
            }
            float mu = s1r * (1.0f / 128.0f);
            float var = s2r * (1.0f / 128.0f) - mu * mu;
            float sc = rsqrtf(var + EPS);
            float4 w4;
            w4.x = (o[0] - mu) * sc * gm.x + bt.x;
            w4.y = (o[1] - mu) * sc * gm.y + bt.y;
            w4.z = (o[2] - mu) * sc * gm.z + bt.z;
            w4.w = (o[3] - mu) * sc * gm.w + bt.w;
            *(float4*)(out + (size_t)e * D + lane * 4) = w4;
        }
    }
}

// ---------------- launch ----------------
extern "C" void kernel_launch(void* const* d_in, const int* in_sizes, int n_in,
                              void* d_out, int out_size) {
    const float* x  = (const float*)d_in[0];
    const int*   ei = (const int*)d_in[1];
    const float* ea = (const float*)d_in[2];
    const float* W  = (const float*)d_in[3];
    const float* b  = (const float*)d_in[4];
    const float* ng = (const float*)d_in[5];
    const float* nb = (const float*)d_in[6];
    const float* eg = (const float*)d_in[7];
    const float* eb = (const float*)d_in[8];
    float* out = (float*)d_out;

    cudaFuncSetAttribute(node_gemm_kernel, cudaFuncAttributeMaxDynamicSharedMemorySize,
                         SMEM_MMA);
    cudaFuncSetAttribute(edge_kernel, cudaFuncAttributeMaxDynamicSharedMemorySize,
                         SMEM_MMA);

    prep_kernel<<<256, 256>>>(W);
    node_ln_kernel<<<(N_NODES + 7) / 8, 256>>>(x, ng, nb);
    node_gemm_kernel<<<dim3((N_NODES + 63) / 64, 2), 512, SMEM_MMA>>>(b);
    edge_kernel<<<(N_EDGES + 63) / 64, 512, SMEM_MMA>>>(ei, ea, eg, eb, out);
}